// round 1
// baseline (speedup 1.0000x reference)
#include <cuda_runtime.h>
#include <cstdint>

// GPTQ v2 4-bit fused dequant + GEMM, fp32 baseline.
// x:        [M, K]   f32   (M = 4*2048 = 8192, K = 4096)
// qweight:  [K/8, N] i32   (8 nibbles packed along K)
// scales:   [K/128, N] f32
// qzeros:   [K/128, N/8] i32 (8 nibbles packed along N; GPTQ adds +1)
// out:      [M, N]   f32
// W[k,n] = s[k/128, n] * (w4[k,n] - (z4[k/128,n] + 1))

#define BM 128
#define BN 128
#define BK 32
#define TM 8
#define TN 8
#define NTHREADS 256

__global__ __launch_bounds__(NTHREADS, 2)
void gptq4_gemm_f32(const float* __restrict__ x,
                    const int*   __restrict__ qweight,
                    const float* __restrict__ scales,
                    const int*   __restrict__ qzeros,
                    float* __restrict__ out,
                    int M, int N, int K)
{
    // +4 pad on As rows to spread store bank conflicts; keeps 16B alignment (132*4=528).
    __shared__ float As[BK][BM + 4];   // k-major: As[k][m]
    __shared__ float Bs[BK][BN];       // k-major: Bs[k][n]

    const int tid = threadIdx.x;
    const int n0  = blockIdx.x * BN;
    const int m0  = blockIdx.y * BM;

    const int tx = tid & 15;   // 16 threads across N
    const int ty = tid >> 4;   // 16 threads across M

    const int NW = N >> 3;     // qzeros row width in int32

    // Per-thread dequant assignment: one B-tile column, two 8-k subrows.
    const int bn   = tid & 127;        // column within tile
    const int bi0  = tid >> 7;         // 0 or 1; also handles bi0+2

    float acc[TM][TN];
    #pragma unroll
    for (int i = 0; i < TM; i++)
        #pragma unroll
        for (int j = 0; j < TN; j++) acc[i][j] = 0.0f;

    for (int k0 = 0; k0 < K; k0 += BK) {
        const int g = k0 >> 7;  // group index (GROUP=128, BK=32 divides it)

        // ---- load A tile: 128 rows x 32 k, float4 along k ----
        {
            const int c4  = (tid & 7) * 4;     // k offset within tile
            const int rwb = tid >> 3;          // row base (0..31)
            #pragma unroll
            for (int p = 0; p < 4; p++) {
                const int row = p * 32 + rwb;
                float4 v = *reinterpret_cast<const float4*>(
                    &x[(size_t)(m0 + row) * K + k0 + c4]);
                As[c4 + 0][row] = v.x;
                As[c4 + 1][row] = v.y;
                As[c4 + 2][row] = v.z;
                As[c4 + 3][row] = v.w;
            }
        }

        // ---- dequant B tile: 32 k x 128 n ----
        {
            const int n = n0 + bn;
            const float s = scales[(size_t)g * N + n];
            const unsigned qzw = (unsigned)qzeros[(size_t)g * NW + (n >> 3)];
            const float zp1 = (float)(((qzw >> ((n & 7) * 4)) & 0xFu) + 1u);
            const float neg = -s * zp1;  // Bs = s*w4 + neg  (one FMA per nibble)

            #pragma unroll
            for (int ii = 0; ii < 2; ii++) {
                const int i = bi0 + ii * 2;  // 0..3: which int32 word along K
                const unsigned qw = (unsigned)qweight[(size_t)(k0 / 8 + i) * N + n];
                #pragma unroll
                for (int j = 0; j < 8; j++) {
                    const float w4 = (float)((qw >> (4 * j)) & 0xFu);
                    Bs[i * 8 + j][bn] = fmaf(s, w4, neg);
                }
            }
        }

        __syncthreads();

        // ---- compute: 8x8 micro-tile per thread ----
        #pragma unroll
        for (int kk = 0; kk < BK; kk++) {
            float a[TM], b[TN];
            const float4* ap = reinterpret_cast<const float4*>(&As[kk][ty * TM]);
            const float4* bp = reinterpret_cast<const float4*>(&Bs[kk][tx * TN]);
            float4 a0 = ap[0], a1 = ap[1];
            float4 b0 = bp[0], b1 = bp[1];
            a[0]=a0.x; a[1]=a0.y; a[2]=a0.z; a[3]=a0.w;
            a[4]=a1.x; a[5]=a1.y; a[6]=a1.z; a[7]=a1.w;
            b[0]=b0.x; b[1]=b0.y; b[2]=b0.z; b[3]=b0.w;
            b[4]=b1.x; b[5]=b1.y; b[6]=b1.z; b[7]=b1.w;
            #pragma unroll
            for (int i = 0; i < TM; i++)
                #pragma unroll
                for (int j = 0; j < TN; j++)
                    acc[i][j] = fmaf(a[i], b[j], acc[i][j]);
        }

        __syncthreads();
    }

    // ---- epilogue: float4 stores ----
    #pragma unroll
    for (int i = 0; i < TM; i++) {
        const size_t row = (size_t)(m0 + ty * TM + i) * N + n0 + tx * TN;
        float4 v0 = make_float4(acc[i][0], acc[i][1], acc[i][2], acc[i][3]);
        float4 v1 = make_float4(acc[i][4], acc[i][5], acc[i][6], acc[i][7]);
        *reinterpret_cast<float4*>(&out[row])     = v0;
        *reinterpret_cast<float4*>(&out[row + 4]) = v1;
    }
}

extern "C" void kernel_launch(void* const* d_in, const int* in_sizes, int n_in,
                              void* d_out, int out_size)
{
    const float* x       = (const float*)d_in[0];
    const int*   qweight = (const int*)  d_in[1];
    const float* scales  = (const float*)d_in[2];
    const int*   qzeros  = (const int*)  d_in[3];
    // d_in[4] = g_idx: known to be arange(K)/128, folded into the kernel.
    float* out = (float*)d_out;

    const int K = 4096;
    const int M = in_sizes[0] / K;              // 8192
    const int N = in_sizes[1] / (K / 8);        // 11008

    dim3 grid(N / BN, M / BM);   // 86 x 64
    gptq4_gemm_f32<<<grid, NTHREADS>>>(x, qweight, scales, qzeros, out, M, N, K);
}

// round 3
// speedup vs baseline: 3.6464x; 3.6464x over previous
#include <cuda_runtime.h>
#include <cuda_fp16.h>
#include <cstdint>

// GPTQ v2 4-bit dequant + GEMM via mma.sync (HMMA fp16, fp32 accum).
// compute_103 base target: tcgen05 unavailable, HMMA is the tensor path.
// x:[8192,4096] f32, qweight:[512,11008] i32, scales:[32,11008] f32,
// qzeros:[32,1376] i32, out:[8192,11008] f32.
// W[k,n] = s * (w4 - (z4+1)), dequanted to fp16; x converted to fp16.

#define N_DIM 11008
#define K_DIM 4096
#define BK 32
#define CHUNKS (K_DIM / BK)     // 128
#define ROWB 80                 // bytes per smem row: 32 halves (64B) + 16B pad
#define MATB (128 * ROWB)       // 10240 B per matrix tile
#define STAGEB (2 * MATB)       // A + B per stage
#define THREADS 256

__device__ __forceinline__ uint32_t smem_u32(const void* p) {
    uint32_t a;
    asm("{ .reg .u64 t; cvta.to.shared.u64 t, %1; cvt.u32.u64 %0, t; }"
        : "=r"(a) : "l"(p));
    return a;
}

#define LDMX4(r, addr)                                                       \
    asm volatile("ldmatrix.sync.aligned.m8n8.x4.shared.b16 {%0,%1,%2,%3}, [%4];" \
        : "=r"((r)[0]), "=r"((r)[1]), "=r"((r)[2]), "=r"((r)[3]) : "r"(addr))

#define MMA16816(d, a, b0, b1)                                               \
    asm volatile("mma.sync.aligned.m16n8k16.row.col.f32.f16.f16.f32 "        \
        "{%0,%1,%2,%3}, {%4,%5,%6,%7}, {%8,%9}, {%0,%1,%2,%3};"              \
        : "+f"((d)[0]), "+f"((d)[1]), "+f"((d)[2]), "+f"((d)[3])             \
        : "r"((a)[0]), "r"((a)[1]), "r"((a)[2]), "r"((a)[3]), "r"(b0), "r"(b1))

#define STS128(addr, r)                                                      \
    asm volatile("st.shared.v4.b32 [%0], {%1,%2,%3,%4};"                     \
        :: "r"(addr), "r"((r)[0]), "r"((r)[1]), "r"((r)[2]), "r"((r)[3]) : "memory")

__device__ __forceinline__ uint32_t pack2(float a, float b) {
    __half2 h = __float22half2_rn(make_float2(a, b));   // memory order: a, b
    return *reinterpret_cast<uint32_t*>(&h);
}

__global__ __launch_bounds__(THREADS, 1)
void gptq4_hmma(const float* __restrict__ x,
                const int*   __restrict__ qweight,
                const float* __restrict__ scales,
                const int*   __restrict__ qzeros,
                float* __restrict__ out)
{
    __shared__ __align__(16) char smem[2 * STAGEB];     // 40 KB
    const uint32_t sb = smem_u32(smem);
    const int tid  = threadIdx.x;
    const int lane = tid & 31;
    const int wid  = tid >> 5;
    const int n0   = blockIdx.x * 128;
    const int m0   = blockIdx.y * 128;

    // ---- producer indexing ----
    // A: thread pair per row; each thread converts 16 consecutive k (fp32->fp16).
    const int arow  = tid >> 1;
    const int ahalf = tid & 1;
    const float* aG = x + (size_t)(m0 + arow) * K_DIM + ahalf * 16;
    const uint32_t aS = sb + (uint32_t)(arow * ROWB + ahalf * 32);

    // B^T: thread owns column n, two packed words (rows rb, rb+2 of the 4-row chunk).
    const int bn = tid & 127;
    const int rb = tid >> 7;
    const int ng = n0 + bn;
    const int qzsh = (ng & 7) * 4;
    const int* qG = qweight + (size_t)rb * N_DIM + ng;
    const uint32_t bS = sb + (uint32_t)MATB + (uint32_t)(bn * ROWB + rb * 16);

    // ---- consumer indexing ----
    const int wm = wid >> 1;          // 0..3  (M)
    const int wn = wid & 1;           // 0..1  (N)
    const int lr = lane & 15;
    const int lsB = (lane >> 4) * 16;
    const uint32_t aLd = sb + (uint32_t)((wm * 32 + lr) * ROWB) + lsB;
    const uint32_t bLd = sb + (uint32_t)MATB + (uint32_t)((wn * 64 + lr) * ROWB) + lsB;

    float acc[2][8][4];
    #pragma unroll
    for (int i = 0; i < 2; i++)
        #pragma unroll
        for (int j = 0; j < 8; j++)
            #pragma unroll
            for (int e = 0; e < 4; e++) acc[i][j][e] = 0.0f;

    // prefetch registers
    float4 av0, av1, av2, av3;
    unsigned qw0, qw1;
    float sc, neg;

    auto LDG = [&](int c) {
        const int k0 = c * BK;
        const float* ap = aG + k0;
        av0 = *(const float4*)(ap);
        av1 = *(const float4*)(ap + 4);
        av2 = *(const float4*)(ap + 8);
        av3 = *(const float4*)(ap + 12);
        const int g = k0 >> 7;
        sc = scales[(size_t)g * N_DIM + ng];
        const unsigned qz = (unsigned)qzeros[(size_t)g * (N_DIM / 8) + (ng >> 3)];
        neg = -sc * (float)(((qz >> qzsh) & 0xFu) + 1u);
        const int* qp = qG + (size_t)(k0 >> 3) * N_DIM;
        qw0 = (unsigned)qp[0];
        qw1 = (unsigned)qp[2 * N_DIM];
    };

    auto STS = [&](int buf) {
        const uint32_t base = buf ? (uint32_t)STAGEB : 0u;
        // A tile
        uint32_t h[8];
        h[0] = pack2(av0.x, av0.y); h[1] = pack2(av0.z, av0.w);
        h[2] = pack2(av1.x, av1.y); h[3] = pack2(av1.z, av1.w);
        h[4] = pack2(av2.x, av2.y); h[5] = pack2(av2.z, av2.w);
        h[6] = pack2(av3.x, av3.y); h[7] = pack2(av3.z, av3.w);
        STS128(aS + base, h);
        STS128(aS + base + 16, h + 4);
        // B^T tile (dequant 16 nibbles)
        #pragma unroll
        for (int w = 0; w < 2; w++) {
            const unsigned q = w ? qw1 : qw0;
            uint32_t bb[4];
            #pragma unroll
            for (int j = 0; j < 4; j++) {
                const float f0 = fmaf(sc, (float)((q >> (8 * j))     & 0xFu), neg);
                const float f1 = fmaf(sc, (float)((q >> (8 * j + 4)) & 0xFu), neg);
                bb[j] = pack2(f0, f1);
            }
            STS128(bS + base + w * 32, bb);   // word w -> k rows (rb+2w)*8..+8
        }
    };

    auto COMPUTE = [&](int buf) {
        const uint32_t base = buf ? (uint32_t)STAGEB : 0u;
        #pragma unroll
        for (int ks = 0; ks < 2; ks++) {
            uint32_t a0[4], a1[4];
            LDMX4(a0, aLd + base + ks * 32);
            LDMX4(a1, aLd + base + ks * 32 + 16 * ROWB);
            uint32_t b[4][4];
            #pragma unroll
            for (int nj = 0; nj < 4; nj++)
                LDMX4(b[nj], bLd + base + ks * 32 + nj * 16 * ROWB);
            #pragma unroll
            for (int nj = 0; nj < 4; nj++) {
                MMA16816(acc[0][2 * nj],     a0, b[nj][0], b[nj][2]);
                MMA16816(acc[0][2 * nj + 1], a0, b[nj][1], b[nj][3]);
                MMA16816(acc[1][2 * nj],     a1, b[nj][0], b[nj][2]);
                MMA16816(acc[1][2 * nj + 1], a1, b[nj][1], b[nj][3]);
            }
        }
    };

    // ---- pipeline: prologue + 128 chunks, double-buffered ----
    LDG(0);
    STS(0);
    __syncthreads();

    #pragma unroll 1
    for (int c = 0; c < CHUNKS; c++) {
        if (c + 1 < CHUNKS) LDG(c + 1);
        COMPUTE(c & 1);
        if (c + 1 < CHUNKS) STS((c + 1) & 1);
        __syncthreads();
    }

    // ---- epilogue: fp32 stores ----
    #pragma unroll
    for (int mi = 0; mi < 2; mi++) {
        const int row = m0 + wm * 32 + mi * 16 + (lane >> 2);
        float* o0 = out + (size_t)row * N_DIM + n0 + wn * 64 + (lane & 3) * 2;
        float* o1 = o0 + (size_t)8 * N_DIM;
        #pragma unroll
        for (int j = 0; j < 8; j++) {
            *(float2*)(o0 + j * 8) = make_float2(acc[mi][j][0], acc[mi][j][1]);
            *(float2*)(o1 + j * 8) = make_float2(acc[mi][j][2], acc[mi][j][3]);
        }
    }
}

extern "C" void kernel_launch(void* const* d_in, const int* in_sizes, int n_in,
                              void* d_out, int out_size)
{
    const float* x       = (const float*)d_in[0];
    const int*   qweight = (const int*)  d_in[1];
    const float* scales  = (const float*)d_in[2];
    const int*   qzeros  = (const int*)  d_in[3];
    float* out = (float*)d_out;

    const int K = 4096;
    const int M = in_sizes[0] / K;          // 8192
    const int N = in_sizes[1] / (K / 8);    // 11008

    dim3 grid(N / 128, M / 128);            // (86, 64)
    gptq4_hmma<<<grid, THREADS>>>(x, qweight, scales, qzeros, out);
}

// round 4
// speedup vs baseline: 4.4087x; 1.2091x over previous
#include <cuda_runtime.h>
#include <cuda_fp16.h>
#include <cstdint>

// GPTQ 4-bit: pre-dequant to fp16 scratch, then cp.async-pipelined HMMA GEMM.
// Pass 1: xh = fp16(x)                 [M,K]  (64 MB)
// Pass 2: wt = fp16(s*(w4-(z4+1)))^T   [N,K]  (90 MB)
// Pass 3: out = xh @ wt^T, mma.sync m16n8k16, fp32 accum.

#define M_DIM 8192
#define N_DIM 11008
#define K_DIM 4096
#define BM 128
#define BN 256
#define BK 32
#define CHUNKS (K_DIM / BK)          // 128
#define ROWB 80                      // 32 halves (64B) + 16B pad per smem row
#define A_BYTES (BM * ROWB)          // 10240
#define B_BYTES (BN * ROWB)          // 20480
#define STAGEB (A_BYTES + B_BYTES)   // 30720
#define STAGES 4
#define SMEM_TOTAL (STAGES * STAGEB) // 122880
#define THREADS 256

__device__ __half g_xh[(size_t)M_DIM * K_DIM];   // 64 MB scratch
__device__ __half g_wt[(size_t)N_DIM * K_DIM];   // 90 MB scratch

__device__ __forceinline__ uint32_t smem_u32(const void* p) {
    uint32_t a;
    asm("{ .reg .u64 t; cvta.to.shared.u64 t, %1; cvt.u32.u64 %0, t; }"
        : "=r"(a) : "l"(p));
    return a;
}

#define LDMX4(r, addr)                                                       \
    asm volatile("ldmatrix.sync.aligned.m8n8.x4.shared.b16 {%0,%1,%2,%3}, [%4];" \
        : "=r"((r)[0]), "=r"((r)[1]), "=r"((r)[2]), "=r"((r)[3]) : "r"(addr))

#define MMA16816(d, a, b0, b1)                                               \
    asm volatile("mma.sync.aligned.m16n8k16.row.col.f32.f16.f16.f32 "        \
        "{%0,%1,%2,%3}, {%4,%5,%6,%7}, {%8,%9}, {%0,%1,%2,%3};"              \
        : "+f"((d)[0]), "+f"((d)[1]), "+f"((d)[2]), "+f"((d)[3])             \
        : "r"((a)[0]), "r"((a)[1]), "r"((a)[2]), "r"((a)[3]), "r"(b0), "r"(b1))

#define CP16(dst, src)                                                       \
    asm volatile("cp.async.cg.shared.global [%0], [%1], 16;"                 \
        :: "r"(dst), "l"(src) : "memory")
#define CP_COMMIT() asm volatile("cp.async.commit_group;" ::: "memory")
#define CP_WAIT2()  asm volatile("cp.async.wait_group 2;" ::: "memory")
#define CP_WAIT0()  asm volatile("cp.async.wait_group 0;" ::: "memory")

__device__ __forceinline__ uint32_t pack2(float a, float b) {
    __half2 h = __float22half2_rn(make_float2(a, b));
    return *reinterpret_cast<uint32_t*>(&h);
}

// ---------- pass 1: x fp32 -> fp16 ----------
__global__ __launch_bounds__(256) void cvt_x_kernel(const float* __restrict__ x) {
    const size_t i = ((size_t)blockIdx.x * 256 + threadIdx.x) * 8;
    const float4 a = *reinterpret_cast<const float4*>(x + i);
    const float4 b = *reinterpret_cast<const float4*>(x + i + 4);
    uint4 o;
    o.x = pack2(a.x, a.y); o.y = pack2(a.z, a.w);
    o.z = pack2(b.x, b.y); o.w = pack2(b.z, b.w);
    *reinterpret_cast<uint4*>(g_xh + i) = o;
}

// ---------- pass 2: dequant to W^T fp16 [N,K] ----------
__global__ __launch_bounds__(256) void dequant_kernel(const int* __restrict__ qweight,
                                                      const float* __restrict__ scales,
                                                      const int* __restrict__ qzeros) {
    const int n  = blockIdx.x * 256 + threadIdx.x;     // 0..11007
    const int kw = blockIdx.y;                          // 0..511 (k-word)
    const int g  = kw >> 4;                             // group = (kw*8)/128
    const float s = scales[(size_t)g * N_DIM + n];
    const unsigned qz = (unsigned)qzeros[(size_t)g * (N_DIM / 8) + (n >> 3)];
    const float neg = -s * (float)(((qz >> ((n & 7) * 4)) & 0xFu) + 1u);
    const unsigned q = (unsigned)qweight[(size_t)kw * N_DIM + n];
    uint4 o;
    uint32_t* p = &o.x;
    #pragma unroll
    for (int j = 0; j < 4; j++) {
        const float f0 = fmaf(s, (float)((q >> (8 * j))     & 0xFu), neg);
        const float f1 = fmaf(s, (float)((q >> (8 * j + 4)) & 0xFu), neg);
        p[j] = pack2(f0, f1);
    }
    *reinterpret_cast<uint4*>(g_wt + (size_t)n * K_DIM + kw * 8) = o;
}

// ---------- pass 3: HMMA GEMM ----------
__global__ __launch_bounds__(THREADS, 1)
void hgemm_main(float* __restrict__ out)
{
    extern __shared__ __align__(16) char smem[];
    const uint32_t sb = smem_u32(smem);
    const int tid  = threadIdx.x;
    const int lane = tid & 31;
    const int wid  = tid >> 5;
    const int m0   = blockIdx.x * BM;
    const int n0   = blockIdx.y * BN;

    // producer addressing (cp.async): A row tid/2 (two 16B segs), B row tid (four 16B segs)
    const __half* aSrc0 = g_xh + (size_t)(m0 + (tid >> 1)) * K_DIM + (tid & 1) * 16;
    const __half* bSrc0 = g_wt + (size_t)(n0 + tid) * K_DIM;
    const uint32_t aDst0 = sb + (uint32_t)((tid >> 1) * ROWB + (tid & 1) * 32);
    const uint32_t bDst0 = sb + (uint32_t)(A_BYTES + tid * ROWB);

    // consumer addressing: 2m x 4n warps, warp tile 64x64
    const int wm = wid & 1;
    const int wn = wid >> 1;
    const int lr  = lane & 15;
    const int lsB = (lane >> 4) * 16;
    const uint32_t aLd0 = sb + (uint32_t)((wm * 64 + lr) * ROWB) + lsB;
    const uint32_t bLd0 = sb + (uint32_t)(A_BYTES + (wn * 64 + lr) * ROWB) + lsB;

    float acc[4][8][4];
    #pragma unroll
    for (int i = 0; i < 4; i++)
        #pragma unroll
        for (int j = 0; j < 8; j++)
            #pragma unroll
            for (int e = 0; e < 4; e++) acc[i][j][e] = 0.0f;

    auto issue = [&](int s, int c) {
        const uint32_t base = (uint32_t)(s * STAGEB);
        const __half* as = aSrc0 + c * BK;
        CP16(aDst0 + base,      as);
        CP16(aDst0 + base + 16, as + 8);
        const __half* bs = bSrc0 + c * BK;
        #pragma unroll
        for (int q = 0; q < 4; q++)
            CP16(bDst0 + base + q * 16, bs + q * 8);
    };

    // prologue: stages 0..2 in flight
    issue(0, 0); CP_COMMIT();
    issue(1, 1); CP_COMMIT();
    issue(2, 2); CP_COMMIT();

    #pragma unroll 1
    for (int c = 0; c < CHUNKS; c++) {
        CP_WAIT2();                       // group c complete -> stage c%4 ready
        __syncthreads();                  // all warps past compute(c-1)
        if (c + 3 < CHUNKS) issue((c + 3) & 3, c + 3);
        CP_COMMIT();

        const uint32_t base = (uint32_t)((c & 3) * STAGEB);
        const uint32_t aLd = aLd0 + base;
        const uint32_t bLd = bLd0 + base;
        #pragma unroll
        for (int ks = 0; ks < 2; ks++) {
            uint32_t a[4][4], b[4][4];
            #pragma unroll
            for (int mi = 0; mi < 4; mi++)
                LDMX4(a[mi], aLd + ks * 32 + mi * 16 * ROWB);
            #pragma unroll
            for (int nj = 0; nj < 4; nj++)
                LDMX4(b[nj], bLd + ks * 32 + nj * 16 * ROWB);
            #pragma unroll
            for (int nj = 0; nj < 4; nj++)
                #pragma unroll
                for (int mi = 0; mi < 4; mi++) {
                    MMA16816(acc[mi][2 * nj],     a[mi], b[nj][0], b[nj][2]);
                    MMA16816(acc[mi][2 * nj + 1], a[mi], b[nj][1], b[nj][3]);
                }
        }
    }
    CP_WAIT0();

    // epilogue
    #pragma unroll
    for (int mi = 0; mi < 4; mi++) {
        const int row = m0 + wm * 64 + mi * 16 + (lane >> 2);
        float* o0 = out + (size_t)row * N_DIM + n0 + wn * 64 + (lane & 3) * 2;
        float* o1 = o0 + (size_t)8 * N_DIM;
        #pragma unroll
        for (int j = 0; j < 8; j++) {
            *(float2*)(o0 + j * 8) = make_float2(acc[mi][j][0], acc[mi][j][1]);
            *(float2*)(o1 + j * 8) = make_float2(acc[mi][j][2], acc[mi][j][3]);
        }
    }
}

extern "C" void kernel_launch(void* const* d_in, const int* in_sizes, int n_in,
                              void* d_out, int out_size)
{
    const float* x       = (const float*)d_in[0];
    const int*   qweight = (const int*)  d_in[1];
    const float* scales  = (const float*)d_in[2];
    const int*   qzeros  = (const int*)  d_in[3];
    float* out = (float*)d_out;

    static bool attr_set = false;
    if (!attr_set) {
        cudaFuncSetAttribute(hgemm_main,
                             cudaFuncAttributeMaxDynamicSharedMemorySize, SMEM_TOTAL);
        attr_set = true;
    }

    cvt_x_kernel<<<(int)((size_t)M_DIM * K_DIM / 8 / 256), 256>>>(x);
    dequant_kernel<<<dim3(N_DIM / 256, K_DIM / 8), 256>>>(qweight, scales, qzeros);

    dim3 grid(M_DIM / BM, N_DIM / BN);   // (64, 43), m-fastest for L2 locality
    hgemm_main<<<grid, THREADS, SMEM_TOTAL>>>(out);
}

// round 5
// speedup vs baseline: 5.5890x; 1.2677x over previous
#include <cuda_runtime.h>
#include <cuda_fp16.h>
#include <cstdint>

// GPTQ 4-bit: pre-dequant to fp16 scratch, then cp.async-pipelined HMMA GEMM.
// Pass 1: xh = fp16(x)                 [M,K]  (64 MB)
// Pass 2: wt = fp16(s*(w4-(z4+1)))^T   [N,K]  (90 MB)
// Pass 3: out = xh @ wt^T, mma.sync m16n8k16, fp32 accum.
// R5: 512 threads / 16 warps per CTA (4 warps/SMSP) to fix issue-starvation;
//     CTA tile 256x128, warp tile 64x32.

#define M_DIM 8192
#define N_DIM 11008
#define K_DIM 4096
#define BM 256
#define BN 128
#define BK 32
#define CHUNKS (K_DIM / BK)          // 128
#define ROWB 80                      // 32 halves (64B) + 16B pad per smem row
#define A_BYTES (BM * ROWB)          // 20480
#define B_BYTES (BN * ROWB)          // 10240
#define STAGEB (A_BYTES + B_BYTES)   // 30720
#define STAGES 4
#define SMEM_TOTAL (STAGES * STAGEB) // 122880
#define THREADS 512

__device__ __half g_xh[(size_t)M_DIM * K_DIM];   // 64 MB scratch
__device__ __half g_wt[(size_t)N_DIM * K_DIM];   // 90 MB scratch

__device__ __forceinline__ uint32_t smem_u32(const void* p) {
    uint32_t a;
    asm("{ .reg .u64 t; cvta.to.shared.u64 t, %1; cvt.u32.u64 %0, t; }"
        : "=r"(a) : "l"(p));
    return a;
}

#define LDMX4(r, addr)                                                       \
    asm volatile("ldmatrix.sync.aligned.m8n8.x4.shared.b16 {%0,%1,%2,%3}, [%4];" \
        : "=r"((r)[0]), "=r"((r)[1]), "=r"((r)[2]), "=r"((r)[3]) : "r"(addr))

#define MMA16816(d, a, b0, b1)                                               \
    asm volatile("mma.sync.aligned.m16n8k16.row.col.f32.f16.f16.f32 "        \
        "{%0,%1,%2,%3}, {%4,%5,%6,%7}, {%8,%9}, {%0,%1,%2,%3};"              \
        : "+f"((d)[0]), "+f"((d)[1]), "+f"((d)[2]), "+f"((d)[3])             \
        : "r"((a)[0]), "r"((a)[1]), "r"((a)[2]), "r"((a)[3]), "r"(b0), "r"(b1))

#define CP16(dst, src)                                                       \
    asm volatile("cp.async.cg.shared.global [%0], [%1], 16;"                 \
        :: "r"(dst), "l"(src) : "memory")
#define CP_COMMIT() asm volatile("cp.async.commit_group;" ::: "memory")
#define CP_WAIT2()  asm volatile("cp.async.wait_group 2;" ::: "memory")
#define CP_WAIT0()  asm volatile("cp.async.wait_group 0;" ::: "memory")

__device__ __forceinline__ uint32_t pack2(float a, float b) {
    __half2 h = __float22half2_rn(make_float2(a, b));
    return *reinterpret_cast<uint32_t*>(&h);
}

// ---------- pass 1: x fp32 -> fp16 ----------
__global__ __launch_bounds__(256) void cvt_x_kernel(const float* __restrict__ x) {
    const size_t i = ((size_t)blockIdx.x * 256 + threadIdx.x) * 8;
    const float4 a = *reinterpret_cast<const float4*>(x + i);
    const float4 b = *reinterpret_cast<const float4*>(x + i + 4);
    uint4 o;
    o.x = pack2(a.x, a.y); o.y = pack2(a.z, a.w);
    o.z = pack2(b.x, b.y); o.w = pack2(b.z, b.w);
    *reinterpret_cast<uint4*>(g_xh + i) = o;
}

// ---------- pass 2: dequant to W^T fp16 [N,K] ----------
__global__ __launch_bounds__(256) void dequant_kernel(const int* __restrict__ qweight,
                                                      const float* __restrict__ scales,
                                                      const int* __restrict__ qzeros) {
    const int n  = blockIdx.x * 256 + threadIdx.x;     // 0..11007
    const int kw = blockIdx.y;                          // 0..511 (k-word)
    const int g  = kw >> 4;                             // group = (kw*8)/128
    const float s = scales[(size_t)g * N_DIM + n];
    const unsigned qz = (unsigned)qzeros[(size_t)g * (N_DIM / 8) + (n >> 3)];
    const float neg = -s * (float)(((qz >> ((n & 7) * 4)) & 0xFu) + 1u);
    const unsigned q = (unsigned)qweight[(size_t)kw * N_DIM + n];
    uint4 o;
    uint32_t* p = &o.x;
    #pragma unroll
    for (int j = 0; j < 4; j++) {
        const float f0 = fmaf(s, (float)((q >> (8 * j))     & 0xFu), neg);
        const float f1 = fmaf(s, (float)((q >> (8 * j + 4)) & 0xFu), neg);
        p[j] = pack2(f0, f1);
    }
    *reinterpret_cast<uint4*>(g_wt + (size_t)n * K_DIM + kw * 8) = o;
}

// ---------- pass 3: HMMA GEMM ----------
__global__ __launch_bounds__(THREADS, 1)
void hgemm_main(float* __restrict__ out)
{
    extern __shared__ __align__(16) char smem[];
    const uint32_t sb = smem_u32(smem);
    const int tid  = threadIdx.x;
    const int lane = tid & 31;
    const int wid  = tid >> 5;
    const int m0   = blockIdx.x * BM;
    const int n0   = blockIdx.y * BN;

    // producer addressing (cp.async)
    // A: 256 rows, thread t -> row t/2, 32B-half t&1 (2 x 16B)
    const __half* aSrc0 = g_xh + (size_t)(m0 + (tid >> 1)) * K_DIM + (tid & 1) * 16;
    const uint32_t aDst0 = sb + (uint32_t)((tid >> 1) * ROWB + (tid & 1) * 32);
    // B: 128 rows, thread t -> row t/4, 16B-seg t&3
    const __half* bSrc0 = g_wt + (size_t)(n0 + (tid >> 2)) * K_DIM + (tid & 3) * 8;
    const uint32_t bDst0 = sb + (uint32_t)(A_BYTES + (tid >> 2) * ROWB + (tid & 3) * 16);

    // consumer addressing: 4m x 4n warps, warp tile 64x32
    const int wm = wid & 3;
    const int wn = wid >> 2;
    const int lr  = lane & 15;
    const int lsB = (lane >> 4) * 16;
    const uint32_t aLd0 = sb + (uint32_t)((wm * 64 + lr) * ROWB) + lsB;
    const uint32_t bLd0 = sb + (uint32_t)(A_BYTES + (wn * 32 + lr) * ROWB) + lsB;

    float acc[4][4][4];
    #pragma unroll
    for (int i = 0; i < 4; i++)
        #pragma unroll
        for (int j = 0; j < 4; j++)
            #pragma unroll
            for (int e = 0; e < 4; e++) acc[i][j][e] = 0.0f;

    auto issue = [&](int s, int c) {
        const uint32_t base = (uint32_t)(s * STAGEB);
        const __half* as = aSrc0 + c * BK;
        CP16(aDst0 + base,      as);
        CP16(aDst0 + base + 16, as + 8);
        CP16(bDst0 + base, bSrc0 + c * BK);
    };

    // prologue: stages 0..2 in flight
    issue(0, 0); CP_COMMIT();
    issue(1, 1); CP_COMMIT();
    issue(2, 2); CP_COMMIT();

    #pragma unroll 1
    for (int c = 0; c < CHUNKS; c++) {
        CP_WAIT2();                       // group c complete -> stage c%4 ready
        __syncthreads();                  // all warps past compute(c-1)
        if (c + 3 < CHUNKS) issue((c + 3) & 3, c + 3);
        CP_COMMIT();

        const uint32_t base = (uint32_t)((c & 3) * STAGEB);
        const uint32_t aLd = aLd0 + base;
        const uint32_t bLd = bLd0 + base;
        #pragma unroll
        for (int ks = 0; ks < 2; ks++) {
            uint32_t a[4][4], b[2][4];
            #pragma unroll
            for (int mi = 0; mi < 4; mi++)
                LDMX4(a[mi], aLd + ks * 32 + mi * 16 * ROWB);
            #pragma unroll
            for (int nj = 0; nj < 2; nj++)
                LDMX4(b[nj], bLd + ks * 32 + nj * 16 * ROWB);
            #pragma unroll
            for (int nj = 0; nj < 2; nj++)
                #pragma unroll
                for (int mi = 0; mi < 4; mi++) {
                    MMA16816(acc[mi][2 * nj],     a[mi], b[nj][0], b[nj][2]);
                    MMA16816(acc[mi][2 * nj + 1], a[mi], b[nj][1], b[nj][3]);
                }
        }
    }
    CP_WAIT0();

    // epilogue
    #pragma unroll
    for (int mi = 0; mi < 4; mi++) {
        const int row = m0 + wm * 64 + mi * 16 + (lane >> 2);
        float* o0 = out + (size_t)row * N_DIM + n0 + wn * 32 + (lane & 3) * 2;
        float* o1 = o0 + (size_t)8 * N_DIM;
        #pragma unroll
        for (int j = 0; j < 4; j++) {
            *(float2*)(o0 + j * 8) = make_float2(acc[mi][j][0], acc[mi][j][1]);
            *(float2*)(o1 + j * 8) = make_float2(acc[mi][j][2], acc[mi][j][3]);
        }
    }
}

extern "C" void kernel_launch(void* const* d_in, const int* in_sizes, int n_in,
                              void* d_out, int out_size)
{
    const float* x       = (const float*)d_in[0];
    const int*   qweight = (const int*)  d_in[1];
    const float* scales  = (const float*)d_in[2];
    const int*   qzeros  = (const int*)  d_in[3];
    float* out = (float*)d_out;

    static bool attr_set = false;
    if (!attr_set) {
        cudaFuncSetAttribute(hgemm_main,
                             cudaFuncAttributeMaxDynamicSharedMemorySize, SMEM_TOTAL);
        attr_set = true;
    }

    cvt_x_kernel<<<(int)((size_t)M_DIM * K_DIM / 8 / 256), 256>>>(x);
    dequant_kernel<<<dim3(N_DIM / 256, K_DIM / 8), 256>>>(qweight, scales, qzeros);

    dim3 grid(M_DIM / BM, N_DIM / BN);   // (32, 86), m-fastest for L2 locality
    hgemm_main<<<grid, THREADS, SMEM_TOTAL>>>(out);
}